// round 11
// baseline (speedup 1.0000x reference)
#include <cuda_runtime.h>
#include <math.h>

#define HIDDEN 128
#define MIX 8
#define MAXN 10000
#define MAXE 512000
#define FULLM 0xffffffffu

// Scratch (allocation-free rule: __device__ globals)
__device__ __align__(16) float g_T[MAXN * MIX];      // per-node hyper weights
__device__ int g_count[MAXN];
__device__ int g_cursor[MAXN];
__device__ int g_offsets[MAXN + 1];
__device__ __align__(8) int2 g_se[MAXE];             // sorted (src, edge_id)
__device__ int g_is64;

__device__ __forceinline__ float gelu_exact(float x) {
    return 0.5f * x * (1.0f + erff(x * 0.70710678118654752f));
}

__device__ __forceinline__ void load_edge(const void* ei, int e, int E, int& s, int& d) {
    if (g_is64) {
        const long long* p = (const long long*)ei;
        s = (int)p[e];
        d = (int)p[(size_t)E + e];
    } else {
        const int* p = (const int*)ei;
        s = p[e];
        d = p[(size_t)E + e];
    }
}

// Zero counters + detect int64-vs-int32 edge_index (node ids < N => int64 high words 0)
__global__ void prep_kernel(const unsigned int* __restrict__ w, int N) {
    int i = blockIdx.x * blockDim.x + threadIdx.x;
    if (i < N) { g_count[i] = 0; g_cursor[i] = 0; }
    if (i == 0) {
        int is64 = 1;
        #pragma unroll
        for (int k = 0; k < 64; k++)
            if (w[2 * k + 1] != 0u) is64 = 0;
        g_is64 = is64;
    }
}

__global__ void hist_kernel(const void* __restrict__ ei, int E) {
    int e = blockIdx.x * blockDim.x + threadIdx.x;
    if (e >= E) return;
    int s, d;
    load_edge(ei, e, E, s, d);
    atomicAdd(&g_count[d], 1);
}

#define SCAN_T 1024
__global__ void scan_kernel(int N) {
    __shared__ int wsum[32];
    int t = threadIdx.x;
    int lane = t & 31, wid = t >> 5;
    int per = (N + SCAN_T - 1) / SCAN_T;
    int beg = t * per;
    int end = min(beg + per, N);

    int local = 0;
    for (int i = beg; i < end; i++) local += g_count[i];

    int v = local;
    #pragma unroll
    for (int off = 1; off < 32; off <<= 1) {
        int u = __shfl_up_sync(FULLM, v, off);
        if (lane >= off) v += u;
    }
    if (lane == 31) wsum[wid] = v;
    __syncthreads();
    if (wid == 0) {
        int wv = wsum[lane];
        #pragma unroll
        for (int off = 1; off < 32; off <<= 1) {
            int u = __shfl_up_sync(FULLM, wv, off);
            if (lane >= off) wv += u;
        }
        wsum[lane] = wv;
    }
    __syncthreads();

    int warp_excl = (wid == 0) ? 0 : wsum[wid - 1];
    int run = warp_excl + (v - local);   // exclusive prefix for this thread
    for (int i = beg; i < end; i++) { g_offsets[i] = run; run += g_count[i]; }
    if (t == SCAN_T - 1) g_offsets[N] = run;
}

__global__ void reorder_kernel(const void* __restrict__ ei, int E) {
    int e = blockIdx.x * blockDim.x + threadIdx.x;
    if (e >= E) return;
    int s, d;
    load_edge(ei, e, E, s, d);
    int pos = g_offsets[d] + atomicAdd(&g_cursor[d], 1);
    g_se[pos] = make_int2(s, e);
}

// T[n,m] = dot( gelu( X[n,:] @ W_A^T ), W_B[m,:] )
__global__ void compute_T_kernel(const float* __restrict__ X,
                                 const float* __restrict__ WA,
                                 const float* __restrict__ WB,
                                 int N) {
    __shared__ float xs[16][HIDDEN];
    __shared__ float gs[16][HIDDEN];
    int t = threadIdx.x;
    int base = blockIdx.x * 16;

    #pragma unroll
    for (int r = 0; r < 16; r++) {
        int n = base + r;
        xs[r][t] = (n < N) ? X[(size_t)n * HIDDEN + t] : 0.f;
    }
    __syncthreads();

    const float* wa = WA + (size_t)t * HIDDEN;
    float acc[16];
    #pragma unroll
    for (int r = 0; r < 16; r++) acc[r] = 0.f;
    for (int k = 0; k < HIDDEN; k++) {
        float w = __ldg(wa + k);
        #pragma unroll
        for (int r = 0; r < 16; r++) acc[r] += xs[r][k] * w;
    }
    #pragma unroll
    for (int r = 0; r < 16; r++) gs[r][t] = gelu_exact(acc[r]);
    __syncthreads();

    int r = t >> 3, m = t & 7;
    int n = base + r;
    if (n < N) {
        const float* wb = WB + (size_t)m * HIDDEN;
        float a = 0.f;
        for (int k = 0; k < HIDDEN; k++) a += gs[r][k] * __ldg(wb + k);
        g_T[(size_t)n * MIX + m] = a;
    }
}

// ONE WARP per dst node. Lane l owns h = 4l..4l+3, all 8 mix accs in regs.
// WARP-COOPERATIVE EDGE FETCH, STATIC UNROLL: one coalesced LDG fetches 16
// edges' (src,eid); a fully-unrolled j=0..15 loop (COMPILE-TIME shfl indices,
// no register arrays) issues 16 independent X/T load chains all rooted at that
// single load -> ptxas front-batches them (MLP~16), amortizing the ~290-cycle
// se->X dependency to ~20 cyc/edge. Out-of-range lanes clamp to the last valid
// edge (loads safe); FMAs/stores are guarded.
#define WPB 4
#define UNR 16
__global__ void __launch_bounds__(32 * WPB, 4)
fused_kernel(const float* __restrict__ X, float* __restrict__ out, int N) {
    int d = blockIdx.x * WPB + (threadIdx.x >> 5);
    if (d >= N) return;
    int lane = threadIdx.x & 31;

    int beg = g_offsets[d];
    int end = g_offsets[d + 1];
    if (beg == end) return;

    float a0[8], a1[8], a2[8], a3[8];
    #pragma unroll
    for (int m = 0; m < 8; m++) { a0[m] = 0.f; a1[m] = 0.f; a2[m] = 0.f; a3[m] = 0.f; }

    // ---- Phase A: agg[d, 4l..4l+3, m] += X[s, 4l..4l+3] * T[s, m] ----
    for (int base = beg; base < end; base += UNR) {
        int last = min(end - base, UNR) - 1;                   // clamp index
        int sv = __ldg(&g_se[base + min(lane, last)].x);       // 1 coalesced LDG / 16 edges

        #pragma unroll
        for (int j = 0; j < UNR; j++) {
            int s = __shfl_sync(FULLM, sv, j);                 // compile-time lane index
            float4 x = __ldg((const float4*)(X + (size_t)s * HIDDEN) + lane);
            const float4* Tp = (const float4*)(g_T + (size_t)s * MIX);
            float4 t0 = __ldg(Tp);
            float4 t1 = __ldg(Tp + 1);
            if (base + j < end) {
                float t[8] = {t0.x, t0.y, t0.z, t0.w, t1.x, t1.y, t1.z, t1.w};
                #pragma unroll
                for (int m = 0; m < 8; m++) {
                    a0[m] = fmaf(x.x, t[m], a0[m]);
                    a1[m] = fmaf(x.y, t[m], a1[m]);
                    a2[m] = fmaf(x.z, t[m], a2[m]);
                    a3[m] = fmaf(x.w, t[m], a3[m]);
                }
            }
        }
    }

    // ---- Phase B: gelu in registers ----
    #pragma unroll
    for (int m = 0; m < 8; m++) {
        a0[m] = gelu_exact(a0[m]);
        a1[m] = gelu_exact(a1[m]);
        a2[m] = gelu_exact(a2[m]);
        a3[m] = gelu_exact(a3[m]);
    }

    // ---- Phase C: out[e, 4l..4l+3] = sum_m agg * T[s_e, m] ----
    for (int base = beg; base < end; base += UNR) {
        int last = min(end - base, UNR) - 1;
        int2 pv = __ldg(&g_se[base + min(lane, last)]);        // 1 coalesced LDG / 16 edges
        int sv = pv.x, ev = pv.y;

        #pragma unroll
        for (int j = 0; j < UNR; j++) {
            int s = __shfl_sync(FULLM, sv, j);
            const float4* Tp = (const float4*)(g_T + (size_t)s * MIX);
            float4 t0 = __ldg(Tp);
            float4 t1 = __ldg(Tp + 1);
            int e = __shfl_sync(FULLM, ev, j);
            if (base + j < end) {
                float t[8] = {t0.x, t0.y, t0.z, t0.w, t1.x, t1.y, t1.z, t1.w};
                float4 r = make_float4(0.f, 0.f, 0.f, 0.f);
                #pragma unroll
                for (int m = 0; m < 8; m++) {
                    r.x = fmaf(a0[m], t[m], r.x);
                    r.y = fmaf(a1[m], t[m], r.y);
                    r.z = fmaf(a2[m], t[m], r.z);
                    r.w = fmaf(a3[m], t[m], r.w);
                }
                *(float4*)(out + (size_t)e * HIDDEN + 4 * lane) = r;
            }
        }
    }
}

// Optional tail: src/dst appended as floats (full-tuple output case)
__global__ void tail_kernel(const void* __restrict__ ei, float* __restrict__ out, int E) {
    int e = blockIdx.x * blockDim.x + threadIdx.x;
    if (e >= E) return;
    int s, d;
    load_edge(ei, e, E, s, d);
    out[(size_t)E * HIDDEN + e] = (float)s;
    out[(size_t)E * HIDDEN + E + e] = (float)d;
}

extern "C" void kernel_launch(void* const* d_in, const int* in_sizes, int n_in,
                              void* d_out, int out_size) {
    const float* X  = (const float*)d_in[0];
    const float* WA = (const float*)d_in[1];
    const float* WB = (const float*)d_in[2];
    const void*  ei = d_in[3];

    int N = in_sizes[0] / HIDDEN;   // 10000
    int E = in_sizes[3] / 2;        // 320000
    float* out = (float*)d_out;

    // Host-side stream/event handles (created once; host objects only, no device mem).
    static cudaStream_t s_side = nullptr;
    static cudaEvent_t ev_fork = nullptr, ev_T = nullptr, ev_r = nullptr, ev_join = nullptr;
    if (s_side == nullptr) {
        cudaStreamCreateWithFlags(&s_side, cudaStreamNonBlocking);
        cudaEventCreateWithFlags(&ev_fork, cudaEventDisableTiming);
        cudaEventCreateWithFlags(&ev_T, cudaEventDisableTiming);
        cudaEventCreateWithFlags(&ev_r, cudaEventDisableTiming);
        cudaEventCreateWithFlags(&ev_join, cudaEventDisableTiming);
    }

    bool want_tail = ((long long)out_size >= (long long)E * (HIDDEN + 2));

    // Main stream (0): prep -> hist -> scan -> reorder -> [wait T] -> fused -> [join]
    // Side stream:     [wait fork] compute_T -> (ev_T) ... [wait reorder] tail -> (ev_join)
    prep_kernel<<<(N + 255) / 256, 256>>>((const unsigned int*)ei, N);
    cudaEventRecord(ev_fork, 0);
    cudaStreamWaitEvent(s_side, ev_fork, 0);

    compute_T_kernel<<<(N + 15) / 16, 128, 0, s_side>>>(X, WA, WB, N);
    cudaEventRecord(ev_T, s_side);

    hist_kernel<<<(E + 255) / 256, 256>>>(ei, E);
    scan_kernel<<<1, SCAN_T>>>(N);
    reorder_kernel<<<(E + 255) / 256, 256>>>(ei, E);
    cudaEventRecord(ev_r, 0);

    cudaStreamWaitEvent(0, ev_T, 0);
    fused_kernel<<<(N + WPB - 1) / WPB, 32 * WPB>>>(X, out, N);

    if (want_tail) {
        cudaStreamWaitEvent(s_side, ev_r, 0);
        tail_kernel<<<(E + 255) / 256, 256, 0, s_side>>>(ei, out, E);
        cudaEventRecord(ev_join, s_side);
        cudaStreamWaitEvent(0, ev_join, 0);
    }
}

// round 12
// speedup vs baseline: 1.1395x; 1.1395x over previous
#include <cuda_runtime.h>
#include <math.h>

#define HIDDEN 128
#define MIX 8
#define MAXN 10000
#define MAXE 512000
#define FULLM 0xffffffffu

// Scratch (allocation-free rule: __device__ globals; zero-initialized at load)
__device__ __align__(16) float g_T[MAXN * MIX];      // per-node hyper weights
__device__ int g_count[MAXN];                        // histogram; reorder restores to 0
__device__ int g_offsets[MAXN + 1];
__device__ __align__(8) int2 g_se[MAXE];             // sorted (src, edge_id)

__device__ __forceinline__ float gelu_exact(float x) {
    return 0.5f * x * (1.0f + erff(x * 0.70710678118654752f));
}

// int64-vs-int32 edge_index detection from the first 32 words. For int64 input,
// odd words are high halves of node ids < N -> all zero. For int32, odd words
// are random node ids; P(16 of them all zero) ~ 1e-64.
__device__ __forceinline__ int detect64(const unsigned int* __restrict__ w) {
    int is64 = 1;
    #pragma unroll
    for (int k = 0; k < 16; k++)
        if (w[2 * k + 1] != 0u) is64 = 0;
    return is64;
}

// Per-block flag via smem (thread 0 pays the 16 broadcast loads once).
#define BLOCK_IS64(ei)                                            \
    __shared__ int s_is64;                                        \
    if (threadIdx.x == 0) s_is64 = detect64((const unsigned int*)(ei)); \
    __syncthreads();

// Histogram of dst; 2 edges per thread, vectorized loads.
__global__ void hist_kernel(const void* __restrict__ ei, int E) {
    BLOCK_IS64(ei);
    int base = (blockIdx.x * blockDim.x + threadIdx.x) * 2;
    if (base >= E) return;
    bool two = (base + 1 < E);
    int d0, d1 = 0;
    if (s_is64) {
        const long long* p = (const long long*)ei + E;   // dst array
        if (two) { longlong2 v = __ldg((const longlong2*)(p + base)); d0 = (int)v.x; d1 = (int)v.y; }
        else d0 = (int)__ldg(p + base);
    } else {
        const int* p = (const int*)ei + E;
        if (two) { int2 v = __ldg((const int2*)(p + base)); d0 = v.x; d1 = v.y; }
        else d0 = __ldg(p + base);
    }
    atomicAdd(&g_count[d0], 1);
    if (two) atomicAdd(&g_count[d1], 1);
}

#define SCAN_T 1024
__global__ void scan_kernel(int N) {
    __shared__ int wsum[32];
    int t = threadIdx.x;
    int lane = t & 31, wid = t >> 5;
    int per = (N + SCAN_T - 1) / SCAN_T;
    int beg = t * per;
    int end = min(beg + per, N);

    int local = 0;
    for (int i = beg; i < end; i++) local += g_count[i];

    int v = local;
    #pragma unroll
    for (int off = 1; off < 32; off <<= 1) {
        int u = __shfl_up_sync(FULLM, v, off);
        if (lane >= off) v += u;
    }
    if (lane == 31) wsum[wid] = v;
    __syncthreads();
    if (wid == 0) {
        int wv = wsum[lane];
        #pragma unroll
        for (int off = 1; off < 32; off <<= 1) {
            int u = __shfl_up_sync(FULLM, wv, off);
            if (lane >= off) wv += u;
        }
        wsum[lane] = wv;
    }
    __syncthreads();

    int warp_excl = (wid == 0) ? 0 : wsum[wid - 1];
    int run = warp_excl + (v - local);   // exclusive prefix for this thread
    for (int i = beg; i < end; i++) { g_offsets[i] = run; run += g_count[i]; }
    if (t == SCAN_T - 1) g_offsets[N] = run;
}

// Scatter edges into dst-sorted order. Position assignment CONSUMES the
// histogram (atomicAdd -1), leaving g_count at 0 for the next graph replay.
__global__ void reorder_kernel(const void* __restrict__ ei, int E) {
    BLOCK_IS64(ei);
    int base = (blockIdx.x * blockDim.x + threadIdx.x) * 2;
    if (base >= E) return;
    bool two = (base + 1 < E);
    int s0, d0, s1 = 0, d1 = 0;
    if (s_is64) {
        const long long* ps = (const long long*)ei;
        const long long* pd = ps + E;
        if (two) {
            longlong2 vs = __ldg((const longlong2*)(ps + base));
            longlong2 vd = __ldg((const longlong2*)(pd + base));
            s0 = (int)vs.x; s1 = (int)vs.y; d0 = (int)vd.x; d1 = (int)vd.y;
        } else { s0 = (int)__ldg(ps + base); d0 = (int)__ldg(pd + base); }
    } else {
        const int* ps = (const int*)ei;
        const int* pd = ps + E;
        if (two) {
            int2 vs = __ldg((const int2*)(ps + base));
            int2 vd = __ldg((const int2*)(pd + base));
            s0 = vs.x; s1 = vs.y; d0 = vd.x; d1 = vd.y;
        } else { s0 = __ldg(ps + base); d0 = __ldg(pd + base); }
    }
    int c0 = atomicAdd(&g_count[d0], -1) - 1;
    g_se[g_offsets[d0] + c0] = make_int2(s0, base);
    if (two) {
        int c1 = atomicAdd(&g_count[d1], -1) - 1;
        g_se[g_offsets[d1] + c1] = make_int2(s1, base + 1);
    }
}

// T[n,m] = dot( gelu( X[n,:] @ W_A^T ), W_B[m,:] )
__global__ void compute_T_kernel(const float* __restrict__ X,
                                 const float* __restrict__ WA,
                                 const float* __restrict__ WB,
                                 int N) {
    __shared__ float xs[16][HIDDEN];
    __shared__ float gs[16][HIDDEN];
    int t = threadIdx.x;
    int base = blockIdx.x * 16;

    #pragma unroll
    for (int r = 0; r < 16; r++) {
        int n = base + r;
        xs[r][t] = (n < N) ? X[(size_t)n * HIDDEN + t] : 0.f;
    }
    __syncthreads();

    const float* wa = WA + (size_t)t * HIDDEN;
    float acc[16];
    #pragma unroll
    for (int r = 0; r < 16; r++) acc[r] = 0.f;
    for (int k = 0; k < HIDDEN; k++) {
        float w = __ldg(wa + k);
        #pragma unroll
        for (int r = 0; r < 16; r++) acc[r] += xs[r][k] * w;
    }
    #pragma unroll
    for (int r = 0; r < 16; r++) gs[r][t] = gelu_exact(acc[r]);
    __syncthreads();

    int r = t >> 3, m = t & 7;
    int n = base + r;
    if (n < N) {
        const float* wb = WB + (size_t)m * HIDDEN;
        float a = 0.f;
        for (int k = 0; k < HIDDEN; k++) a += gs[r][k] * __ldg(wb + k);
        g_T[(size_t)n * MIX + m] = a;
    }
}

// ONE WARP per dst node. Lane l owns h = 4l..4l+3, all 8 mix accs in regs.
// SOFTWARE-PIPELINED depth-1 (R8 structure — the measured best inner loop).
#define WPB 4
__global__ void __launch_bounds__(32 * WPB, 4)
fused_kernel(const float* __restrict__ X, float* __restrict__ out, int N) {
    int d = blockIdx.x * WPB + (threadIdx.x >> 5);
    if (d >= N) return;
    int lane = threadIdx.x & 31;

    int beg = g_offsets[d];
    int end = g_offsets[d + 1];
    if (beg == end) return;

    float a0[8], a1[8], a2[8], a3[8];
    #pragma unroll
    for (int m = 0; m < 8; m++) { a0[m] = 0.f; a1[m] = 0.f; a2[m] = 0.f; a3[m] = 0.f; }

    // ---- Phase A (pipelined): agg[d, 4l..4l+3, m] += X[s, 4l..4l+3] * T[s, m] ----
    {
        int sc = __ldg(&g_se[beg].x);
        float4 xc = __ldg((const float4*)(X + (size_t)sc * HIDDEN) + lane);
        const float4* Tc = (const float4*)(g_T + (size_t)sc * MIX);
        float4 tc0 = __ldg(Tc), tc1 = __ldg(Tc + 1);

        for (int i = beg; i < end - 1; i++) {
            int sn = __ldg(&g_se[i + 1].x);
            float4 xn = __ldg((const float4*)(X + (size_t)sn * HIDDEN) + lane);
            const float4* Tn = (const float4*)(g_T + (size_t)sn * MIX);
            float4 tn0 = __ldg(Tn), tn1 = __ldg(Tn + 1);

            float t[8] = {tc0.x, tc0.y, tc0.z, tc0.w, tc1.x, tc1.y, tc1.z, tc1.w};
            #pragma unroll
            for (int m = 0; m < 8; m++) {
                a0[m] = fmaf(xc.x, t[m], a0[m]);
                a1[m] = fmaf(xc.y, t[m], a1[m]);
                a2[m] = fmaf(xc.z, t[m], a2[m]);
                a3[m] = fmaf(xc.w, t[m], a3[m]);
            }
            xc = xn; tc0 = tn0; tc1 = tn1;
        }
        float t[8] = {tc0.x, tc0.y, tc0.z, tc0.w, tc1.x, tc1.y, tc1.z, tc1.w};
        #pragma unroll
        for (int m = 0; m < 8; m++) {
            a0[m] = fmaf(xc.x, t[m], a0[m]);
            a1[m] = fmaf(xc.y, t[m], a1[m]);
            a2[m] = fmaf(xc.z, t[m], a2[m]);
            a3[m] = fmaf(xc.w, t[m], a3[m]);
        }
    }

    // ---- Phase B: gelu in registers ----
    #pragma unroll
    for (int m = 0; m < 8; m++) {
        a0[m] = gelu_exact(a0[m]);
        a1[m] = gelu_exact(a1[m]);
        a2[m] = gelu_exact(a2[m]);
        a3[m] = gelu_exact(a3[m]);
    }

    // ---- Phase C (pipelined): out[e, 4l..4l+3] = sum_m agg * T[s_e, m] ----
    {
        int2 pc = __ldg(&g_se[beg]);
        const float4* Tc = (const float4*)(g_T + (size_t)pc.x * MIX);
        float4 tc0 = __ldg(Tc), tc1 = __ldg(Tc + 1);

        for (int i = beg; i < end - 1; i++) {
            int2 pn = __ldg(&g_se[i + 1]);
            const float4* Tn = (const float4*)(g_T + (size_t)pn.x * MIX);
            float4 tn0 = __ldg(Tn), tn1 = __ldg(Tn + 1);

            float t[8] = {tc0.x, tc0.y, tc0.z, tc0.w, tc1.x, tc1.y, tc1.z, tc1.w};
            float4 r = make_float4(0.f, 0.f, 0.f, 0.f);
            #pragma unroll
            for (int m = 0; m < 8; m++) {
                r.x = fmaf(a0[m], t[m], r.x);
                r.y = fmaf(a1[m], t[m], r.y);
                r.z = fmaf(a2[m], t[m], r.z);
                r.w = fmaf(a3[m], t[m], r.w);
            }
            *(float4*)(out + (size_t)pc.y * HIDDEN + 4 * lane) = r;
            pc = pn; tc0 = tn0; tc1 = tn1;
        }
        float t[8] = {tc0.x, tc0.y, tc0.z, tc0.w, tc1.x, tc1.y, tc1.z, tc1.w};
        float4 r = make_float4(0.f, 0.f, 0.f, 0.f);
        #pragma unroll
        for (int m = 0; m < 8; m++) {
            r.x = fmaf(a0[m], t[m], r.x);
            r.y = fmaf(a1[m], t[m], r.y);
            r.z = fmaf(a2[m], t[m], r.z);
            r.w = fmaf(a3[m], t[m], r.w);
        }
        *(float4*)(out + (size_t)pc.y * HIDDEN + 4 * lane) = r;
    }
}

// Optional tail: src/dst appended as floats (full-tuple output case)
__global__ void tail_kernel(const void* __restrict__ ei, float* __restrict__ out, int E) {
    BLOCK_IS64(ei);
    int e = blockIdx.x * blockDim.x + threadIdx.x;
    if (e >= E) return;
    int s, d;
    if (s_is64) {
        const long long* p = (const long long*)ei;
        s = (int)__ldg(p + e);
        d = (int)__ldg(p + E + e);
    } else {
        const int* p = (const int*)ei;
        s = __ldg(p + e);
        d = __ldg(p + E + e);
    }
    out[(size_t)E * HIDDEN + e] = (float)s;
    out[(size_t)E * HIDDEN + E + e] = (float)d;
}

extern "C" void kernel_launch(void* const* d_in, const int* in_sizes, int n_in,
                              void* d_out, int out_size) {
    const float* X  = (const float*)d_in[0];
    const float* WA = (const float*)d_in[1];
    const float* WB = (const float*)d_in[2];
    const void*  ei = d_in[3];

    int N = in_sizes[0] / HIDDEN;   // 10000
    int E = in_sizes[3] / 2;        // 320000
    float* out = (float*)d_out;

    // Host-side stream/event handles (created once; host objects only, no device mem).
    static cudaStream_t s_side = nullptr;
    static cudaEvent_t ev_fork = nullptr, ev_T = nullptr, ev_r = nullptr, ev_join = nullptr;
    if (s_side == nullptr) {
        cudaStreamCreateWithFlags(&s_side, cudaStreamNonBlocking);
        cudaEventCreateWithFlags(&ev_fork, cudaEventDisableTiming);
        cudaEventCreateWithFlags(&ev_T, cudaEventDisableTiming);
        cudaEventCreateWithFlags(&ev_r, cudaEventDisableTiming);
        cudaEventCreateWithFlags(&ev_join, cudaEventDisableTiming);
    }

    bool want_tail = ((long long)out_size >= (long long)E * (HIDDEN + 2));

    // Main stream (0): hist -> scan -> reorder -> [wait T] -> fused -> [join]
    // Side stream:     [fork] compute_T -> (ev_T) ... [wait reorder] tail -> (ev_join)
    cudaEventRecord(ev_fork, 0);
    cudaStreamWaitEvent(s_side, ev_fork, 0);

    compute_T_kernel<<<(N + 15) / 16, 128, 0, s_side>>>(X, WA, WB, N);
    cudaEventRecord(ev_T, s_side);

    int half_threads = (E + 1) / 2;
    hist_kernel<<<(half_threads + 255) / 256, 256>>>(ei, E);
    scan_kernel<<<1, SCAN_T>>>(N);
    reorder_kernel<<<(half_threads + 255) / 256, 256>>>(ei, E);
    cudaEventRecord(ev_r, 0);

    cudaStreamWaitEvent(0, ev_T, 0);
    fused_kernel<<<(N + WPB - 1) / WPB, 32 * WPB>>>(X, out, N);

    if (want_tail) {
        cudaStreamWaitEvent(s_side, ev_r, 0);
        tail_kernel<<<(E + 255) / 256, 256, 0, s_side>>>(ei, out, E);
        cudaEventRecord(ev_join, s_side);
        cudaStreamWaitEvent(0, ev_join, 0);
    }
}

// round 13
// speedup vs baseline: 1.1615x; 1.0193x over previous
#include <cuda_runtime.h>
#include <math.h>

#define HIDDEN 128
#define MIX 8
#define MAXN 10000
#define MAXE 512000
#define FULLM 0xffffffffu

// Scratch (allocation-free rule: __device__ globals)
__device__ __align__(16) float g_T[MAXN * MIX];      // per-node hyper weights
__device__ int g_count[MAXN];
__device__ int g_cursor[MAXN];
__device__ int g_offsets[MAXN + 1];
__device__ __align__(8) int2 g_se[MAXE];             // sorted (src, edge_id)
__device__ int g_is64;

__device__ __forceinline__ float gelu_exact(float x) {
    return 0.5f * x * (1.0f + erff(x * 0.70710678118654752f));
}

__device__ __forceinline__ void load_edge(const void* ei, int e, int E, int& s, int& d) {
    if (g_is64) {
        const long long* p = (const long long*)ei;
        s = (int)p[e];
        d = (int)p[(size_t)E + e];
    } else {
        const int* p = (const int*)ei;
        s = p[e];
        d = p[(size_t)E + e];
    }
}

// Zero counters + detect int64-vs-int32 edge_index (node ids < N => int64 high words 0)
__global__ void prep_kernel(const unsigned int* __restrict__ w, int N) {
    int i = blockIdx.x * blockDim.x + threadIdx.x;
    if (i < N) { g_count[i] = 0; g_cursor[i] = 0; }
    if (i == 0) {
        int is64 = 1;
        #pragma unroll
        for (int k = 0; k < 64; k++)
            if (w[2 * k + 1] != 0u) is64 = 0;
        g_is64 = is64;
    }
}

__global__ void hist_kernel(const void* __restrict__ ei, int E) {
    int e = blockIdx.x * blockDim.x + threadIdx.x;
    if (e >= E) return;
    int s, d;
    load_edge(ei, e, E, s, d);
    atomicAdd(&g_count[d], 1);
}

#define SCAN_T 1024
__global__ void scan_kernel(int N) {
    __shared__ int wsum[32];
    int t = threadIdx.x;
    int lane = t & 31, wid = t >> 5;
    int per = (N + SCAN_T - 1) / SCAN_T;
    int beg = t * per;
    int end = min(beg + per, N);

    int local = 0;
    for (int i = beg; i < end; i++) local += g_count[i];

    int v = local;
    #pragma unroll
    for (int off = 1; off < 32; off <<= 1) {
        int u = __shfl_up_sync(FULLM, v, off);
        if (lane >= off) v += u;
    }
    if (lane == 31) wsum[wid] = v;
    __syncthreads();
    if (wid == 0) {
        int wv = wsum[lane];
        #pragma unroll
        for (int off = 1; off < 32; off <<= 1) {
            int u = __shfl_up_sync(FULLM, wv, off);
            if (lane >= off) wv += u;
        }
        wsum[lane] = wv;
    }
    __syncthreads();

    int warp_excl = (wid == 0) ? 0 : wsum[wid - 1];
    int run = warp_excl + (v - local);   // exclusive prefix for this thread
    for (int i = beg; i < end; i++) { g_offsets[i] = run; run += g_count[i]; }
    if (t == SCAN_T - 1) g_offsets[N] = run;
}

__global__ void reorder_kernel(const void* __restrict__ ei, int E) {
    int e = blockIdx.x * blockDim.x + threadIdx.x;
    if (e >= E) return;
    int s, d;
    load_edge(ei, e, E, s, d);
    int pos = g_offsets[d] + atomicAdd(&g_cursor[d], 1);
    g_se[pos] = make_int2(s, e);
}

// T[n,m] = dot( gelu( X[n,:] @ W_A^T ), W_B[m,:] )
__global__ void compute_T_kernel(const float* __restrict__ X,
                                 const float* __restrict__ WA,
                                 const float* __restrict__ WB,
                                 int N) {
    __shared__ float xs[16][HIDDEN];
    __shared__ float gs[16][HIDDEN];
    int t = threadIdx.x;
    int base = blockIdx.x * 16;

    #pragma unroll
    for (int r = 0; r < 16; r++) {
        int n = base + r;
        xs[r][t] = (n < N) ? X[(size_t)n * HIDDEN + t] : 0.f;
    }
    __syncthreads();

    const float* wa = WA + (size_t)t * HIDDEN;
    float acc[16];
    #pragma unroll
    for (int r = 0; r < 16; r++) acc[r] = 0.f;
    for (int k = 0; k < HIDDEN; k++) {
        float w = __ldg(wa + k);
        #pragma unroll
        for (int r = 0; r < 16; r++) acc[r] += xs[r][k] * w;
    }
    #pragma unroll
    for (int r = 0; r < 16; r++) gs[r][t] = gelu_exact(acc[r]);
    __syncthreads();

    int r = t >> 3, m = t & 7;
    int n = base + r;
    if (n < N) {
        const float* wb = WB + (size_t)m * HIDDEN;
        float a = 0.f;
        for (int k = 0; k < HIDDEN; k++) a += gs[r][k] * __ldg(wb + k);
        g_T[(size_t)n * MIX + m] = a;
    }
}

// ONE WARP per dst node. Lane l owns h = 4l..4l+3, all 8 mix accs in regs.
// DEPTH-2 software pipeline with THREE EXPLICIT SCALAR SLOTS (consume / next /
// incoming) rotated by register moves — no arrays (no local-mem demotion),
// occupancy unchanged vs R8. Lookahead doubles to ~2 edges (~128 FMA-cyc),
// covering the loaded-L2 gather window at 4 warps/SMSP.
#define WPB 4
__global__ void __launch_bounds__(32 * WPB, 4)
fused_kernel(const float* __restrict__ X, float* __restrict__ out, int N) {
    int d = blockIdx.x * WPB + (threadIdx.x >> 5);
    if (d >= N) return;
    int lane = threadIdx.x & 31;

    int beg = g_offsets[d];
    int end = g_offsets[d + 1];
    if (beg == end) return;
    int last = end - 1;

    float a0[8], a1[8], a2[8], a3[8];
    #pragma unroll
    for (int m = 0; m < 8; m++) { a0[m] = 0.f; a1[m] = 0.f; a2[m] = 0.f; a3[m] = 0.f; }

    // ---- Phase A (depth-2 pipelined): agg += X[s, 4l..4l+3] * T[s, m] ----
    {
        // slot C = edge beg, slot N = edge beg+1 (clamped)
        int sc = __ldg(&g_se[beg].x);
        float4 xc = __ldg((const float4*)(X + (size_t)sc * HIDDEN) + lane);
        const float4* Tc = (const float4*)(g_T + (size_t)sc * MIX);
        float4 tc0 = __ldg(Tc), tc1 = __ldg(Tc + 1);

        int i1 = min(beg + 1, last);
        int sn = __ldg(&g_se[i1].x);
        float4 xn = __ldg((const float4*)(X + (size_t)sn * HIDDEN) + lane);
        const float4* Tn = (const float4*)(g_T + (size_t)sn * MIX);
        float4 tn0 = __ldg(Tn), tn1 = __ldg(Tn + 1);

        for (int i = beg; i < end; i++) {
            // prefetch edge i+2 into slot M (clamped; wasted only at tail)
            int im = min(i + 2, last);
            int sm = __ldg(&g_se[im].x);
            float4 xm = __ldg((const float4*)(X + (size_t)sm * HIDDEN) + lane);
            const float4* Tm = (const float4*)(g_T + (size_t)sm * MIX);
            float4 tm0 = __ldg(Tm), tm1 = __ldg(Tm + 1);

            // consume slot C (edge i)
            float t[8] = {tc0.x, tc0.y, tc0.z, tc0.w, tc1.x, tc1.y, tc1.z, tc1.w};
            #pragma unroll
            for (int m = 0; m < 8; m++) {
                a0[m] = fmaf(xc.x, t[m], a0[m]);
                a1[m] = fmaf(xc.y, t[m], a1[m]);
                a2[m] = fmaf(xc.z, t[m], a2[m]);
                a3[m] = fmaf(xc.w, t[m], a3[m]);
            }
            // rotate slots
            xc = xn; tc0 = tn0; tc1 = tn1;
            xn = xm; tn0 = tm0; tn1 = tm1;
        }
    }

    // ---- Phase B: gelu in registers ----
    #pragma unroll
    for (int m = 0; m < 8; m++) {
        a0[m] = gelu_exact(a0[m]);
        a1[m] = gelu_exact(a1[m]);
        a2[m] = gelu_exact(a2[m]);
        a3[m] = gelu_exact(a3[m]);
    }

    // ---- Phase C (depth-2 pipelined): out[e, 4l..4l+3] = sum_m agg * T[s_e, m] ----
    {
        int2 pc = __ldg(&g_se[beg]);
        const float4* Tc = (const float4*)(g_T + (size_t)pc.x * MIX);
        float4 tc0 = __ldg(Tc), tc1 = __ldg(Tc + 1);

        int i1 = min(beg + 1, last);
        int2 pn = __ldg(&g_se[i1]);
        const float4* Tn = (const float4*)(g_T + (size_t)pn.x * MIX);
        float4 tn0 = __ldg(Tn), tn1 = __ldg(Tn + 1);

        for (int i = beg; i < end; i++) {
            int im = min(i + 2, last);
            int2 pm = __ldg(&g_se[im]);
            const float4* Tm = (const float4*)(g_T + (size_t)pm.x * MIX);
            float4 tm0 = __ldg(Tm), tm1 = __ldg(Tm + 1);

            float t[8] = {tc0.x, tc0.y, tc0.z, tc0.w, tc1.x, tc1.y, tc1.z, tc1.w};
            float4 r = make_float4(0.f, 0.f, 0.f, 0.f);
            #pragma unroll
            for (int m = 0; m < 8; m++) {
                r.x = fmaf(a0[m], t[m], r.x);
                r.y = fmaf(a1[m], t[m], r.y);
                r.z = fmaf(a2[m], t[m], r.z);
                r.w = fmaf(a3[m], t[m], r.w);
            }
            *(float4*)(out + (size_t)pc.y * HIDDEN + 4 * lane) = r;

            pc = pn; tc0 = tn0; tc1 = tn1;
            pn = pm; tn0 = tm0; tn1 = tm1;
        }
    }
}

// Optional tail: src/dst appended as floats (full-tuple output case)
__global__ void tail_kernel(const void* __restrict__ ei, float* __restrict__ out, int E) {
    int e = blockIdx.x * blockDim.x + threadIdx.x;
    if (e >= E) return;
    int s, d;
    load_edge(ei, e, E, s, d);
    out[(size_t)E * HIDDEN + e] = (float)s;
    out[(size_t)E * HIDDEN + E + e] = (float)d;
}

extern "C" void kernel_launch(void* const* d_in, const int* in_sizes, int n_in,
                              void* d_out, int out_size) {
    const float* X  = (const float*)d_in[0];
    const float* WA = (const float*)d_in[1];
    const float* WB = (const float*)d_in[2];
    const void*  ei = d_in[3];

    int N = in_sizes[0] / HIDDEN;   // 10000
    int E = in_sizes[3] / 2;        // 320000
    float* out = (float*)d_out;

    // Host-side stream/event handles (created once; host objects only, no device mem).
    static cudaStream_t s_side = nullptr;
    static cudaEvent_t ev_fork = nullptr, ev_T = nullptr, ev_r = nullptr, ev_join = nullptr;
    if (s_side == nullptr) {
        cudaStreamCreateWithFlags(&s_side, cudaStreamNonBlocking);
        cudaEventCreateWithFlags(&ev_fork, cudaEventDisableTiming);
        cudaEventCreateWithFlags(&ev_T, cudaEventDisableTiming);
        cudaEventCreateWithFlags(&ev_r, cudaEventDisableTiming);
        cudaEventCreateWithFlags(&ev_join, cudaEventDisableTiming);
    }

    bool want_tail = ((long long)out_size >= (long long)E * (HIDDEN + 2));

    // Main stream (0): prep -> hist -> scan -> reorder -> [wait T] -> fused -> [join]
    // Side stream:     [wait fork] compute_T -> (ev_T) ... [wait reorder] tail -> (ev_join)
    prep_kernel<<<(N + 255) / 256, 256>>>((const unsigned int*)ei, N);
    cudaEventRecord(ev_fork, 0);
    cudaStreamWaitEvent(s_side, ev_fork, 0);

    compute_T_kernel<<<(N + 15) / 16, 128, 0, s_side>>>(X, WA, WB, N);
    cudaEventRecord(ev_T, s_side);

    hist_kernel<<<(E + 255) / 256, 256>>>(ei, E);
    scan_kernel<<<1, SCAN_T>>>(N);
    reorder_kernel<<<(E + 255) / 256, 256>>>(ei, E);
    cudaEventRecord(ev_r, 0);

    cudaStreamWaitEvent(0, ev_T, 0);
    fused_kernel<<<(N + WPB - 1) / WPB, 32 * WPB>>>(X, out, N);

    if (want_tail) {
        cudaStreamWaitEvent(s_side, ev_r, 0);
        tail_kernel<<<(E + 255) / 256, 256, 0, s_side>>>(ei, out, E);
        cudaEventRecord(ev_join, s_side);
        cudaStreamWaitEvent(0, ev_join, 0);
    }
}